// round 16
// baseline (speedup 1.0000x reference)
#include <cuda_runtime.h>
#include <stdint.h>

// BallPointQuery: B=4, N=16384, M=2048, MAX_SAMPLES=64, RADIUS=0.2
// pcs float32 [B,N,3]; centroids float32 [B,M,3]
// Output: float32 [B,M,64] (indices stored as floats; established R8).
//
// Hit test algebra: d2 <= r2  <=>  cross - p2/2 >= (c2 - r2)/2.
// Pack stores (x, y, z, -p2/2): test is 3 FFMA + SETP per point.
// Persistent warps + atomic work stealing smooth the drain tail.
// Inner loop is 2x unrolled (512 pts) with structural double buffering:
// zero register-copy MOVs, loads issue one full chunk ahead of use.

#define BQ_B 4
#define BQ_N 16384
#define BQ_M 2048
#define BQ_S 64

// +512 pad: the deepest prefetch reads [N, N+512) — loaded, never consumed.
__device__ float4 g_pack[BQ_B * BQ_N + 512];
__device__ unsigned g_ctr;

__global__ __launch_bounds__(256)
void pack_kernel(const float* __restrict__ pcs)
{
    const int i = blockIdx.x * blockDim.x + threadIdx.x;
    if (i == 0) g_ctr = 0;   // stream-ordered reset before the query kernel
    if (i >= BQ_B * BQ_N) return;
    const float px = pcs[i * 3 + 0];
    const float py = pcs[i * 3 + 1];
    const float pz = pcs[i * 3 + 2];
    const float p2 = fmaf(pz, pz, fmaf(py, py, px * px));
    g_pack[i] = make_float4(px, py, pz, -0.5f * p2);
}

__global__ __launch_bounds__(64)
void ball_query_kernel(const float* __restrict__ cents,
                       float* __restrict__ out)
{
    const int lane = threadIdx.x & 31;
    const unsigned below = (1u << lane) - 1u;

    for (;;) {
        int task;
        if (lane == 0) task = (int)atomicAdd(&g_ctr, 1u);
        task = __shfl_sync(0xffffffffu, task, 0);
        if (task >= BQ_B * BQ_M) return;

        const int b = task >> 11;          // / BQ_M

        const int cbase = task * 3;
        const float cx = cents[cbase + 0];
        const float cy = cents[cbase + 1];
        const float cz = cents[cbase + 2];

        const float c2 = fmaf(cz, cz, fmaf(cy, cy, cx * cx));
        const float r2 = (float)(0.2 * 0.2);
        const float thr = 0.5f * (c2 - r2);   // hit <=> fma-chain >= thr

        float* __restrict__ o = out + task * BQ_S;
        const float4* __restrict__ p = g_pack + b * BQ_N + lane;

        int count = 0;
        int first = BQ_N;

        // Process one 256-point chunk held in regs; returns true when full.
        auto process = [&](const float4 (&a)[8], int base) -> bool {
            float s[8];
            #pragma unroll
            for (int g = 0; g < 8; g++)
                s[g] = fmaf(cx, a[g].x, fmaf(cy, a[g].y, fmaf(cz, a[g].z, a[g].w)));

            bool h[8];
            unsigned msk[8];
            unsigned any = 0u;
            #pragma unroll
            for (int g = 0; g < 8; g++) {
                h[g] = (s[g] >= thr);
                msk[g] = __ballot_sync(0xffffffffu, h[g]);
                any |= msk[g];
            }

            if (any) {
                if (count == 0) {
                    #pragma unroll
                    for (int g = 7; g >= 0; g--)
                        if (msk[g]) first = base + g * 32 + (__ffs(msk[g]) - 1);
                }
                int c = count;
                #pragma unroll
                for (int g = 0; g < 8; g++) {
                    if (h[g]) {
                        const int slot = c + __popc(msk[g] & below);
                        if (slot < BQ_S) o[slot] = (float)(base + g * 32 + lane);
                    }
                    c += __popc(msk[g]);
                }
                count = c;
                if (count >= BQ_S) return true;
            }
            return false;
        };

        float4 A[8], Bf[8];
        #pragma unroll
        for (int g = 0; g < 8; g++) A[g] = p[g * 32];          // chunk 0

        for (int base = 0; base < BQ_N; base += 512) {
            #pragma unroll
            for (int g = 0; g < 8; g++) Bf[g] = p[256 + g * 32];  // chunk base+256
            if (process(A, base)) break;

            #pragma unroll
            for (int g = 0; g < 8; g++) A[g] = p[512 + g * 32];   // chunk base+512
            if (process(Bf, base + 256)) break;

            p += 512;
        }

        const float padv = (float)first;
        #pragma unroll
        for (int s2 = lane; s2 < BQ_S; s2 += 32) {
            if (s2 >= count) o[s2] = padv;
        }
    }
}

extern "C" void kernel_launch(void* const* d_in, const int* in_sizes, int n_in,
                              void* d_out, int out_size)
{
    // Bind by RELATIVE size: pcs is the largest buffer, centroids second.
    int pi = 0, ci = (n_in > 1) ? 1 : 0;
    if (n_in >= 2) {
        int i0 = 0;
        for (int i = 1; i < n_in; i++)
            if (in_sizes[i] > in_sizes[i0]) i0 = i;
        int i1 = (i0 == 0) ? 1 : 0;
        for (int i = 0; i < n_in; i++)
            if (i != i0 && in_sizes[i] > in_sizes[i1]) i1 = i;
        pi = i0;
        ci = i1;
    }
    const float* pcs   = (const float*)d_in[pi];
    const float* cents = (const float*)d_in[ci];
    float* out = (float*)d_out;

    const int npts = BQ_B * BQ_N;                   // 65536 threads, 256 blocks
    pack_kernel<<<(npts + 255) / 256, 256>>>(pcs);

    // Persistent grid; work stealing makes the exact count non-critical.
    const int blocks = 152 * 12;                     // ~reg-limited residency
    ball_query_kernel<<<blocks, 64>>>(cents, out);
}